// round 15
// baseline (speedup 1.0000x reference)
#include <cuda_runtime.h>
#include <cstdint>

#define NN    128
#define BATCH 2
#define LSEQ  2048
#define CL    32
#define PCH   (LSEQ/CL)   // 64 chunks per batch

typedef unsigned long long u64;

// packed f32x2 FMA (sm_103a FFMA2): d.lo += a.lo*b.lo ; d.hi += a.hi*b.hi
__device__ __forceinline__ void ffma2(u64& d, u64 a, u64 b) {
    asm("fma.rn.f32x2 %0, %1, %2, %0;" : "+l"(d) : "l"(a), "l"(b));
}
__device__ __forceinline__ float f2lo(u64 a){ return __int_as_float((int)(unsigned)(a & 0xffffffffull)); }
__device__ __forceinline__ float f2hi(u64 a){ return __int_as_float((int)(unsigned)(a >> 32)); }

// ---------------- device scratch (no allocations allowed) ----------------
// Ad packed: double2 element [m*NN+n] holds Ad[n][4m..4m+3] as 4 floats.
__device__ double2 g_Ad2[32*NN];
__device__ double2 g_M32[32*NN];                  // Ad^32, same layout
__device__ float   g_Bd[NN];
__device__ float   g_lend[BATCH*PCH*NN];          // chunk-end local states
__device__ float   g_carry[BATCH*PCH*NN];

// ---------------- setup: GBT discretization (fp32 forward substitution) --
// P1 = I - 0.5*A is lower triangular (HiPPO-LegS). Block j solves column j
// of P1*Ad = I + 0.5*A (j<128) or P1*Bd = B (j==128). Division-free chain.
__global__ __launch_bounds__(NN) void k_solve(const float* __restrict__ A,
                                              const float* __restrict__ Bv) {
    int j = blockIdx.x, i = threadIdx.x;
    __shared__ float AT_s[NN*(NN+1)/2 + 1];   // packed lower triangle (+1 pad)
    __shared__ float sh[2];

    for (int idx = i; idx < NN*NN; idx += NN) {
        int r = idx >> 7, c = idx & 127;
        if (c <= r) AT_s[r*(r+1)/2 + c] = A[idx];
    }
    __syncthreads();

    int tri_i = i*(i+1)/2;
    float rdiag = 1.f / (1.f - 0.5f * AT_s[tri_i + i]);
    float hrd   = 0.5f * rdiag;

    float rhs;
    if (j < NN) rhs = (i == j ? 1.f : 0.f) + 0.5f * A[i*NN + j];
    else        rhs = Bv[i];
    float y = rhs * rdiag;

    float at = AT_s[tri_i];   // A[i][0]
    #pragma unroll 4
    for (int k = 0; k < NN; k++) {
        float coef = hrd * at;              // off critical path
        if (i == k) sh[k & 1] = y;
        at = AT_s[tri_i + k + 1];           // prefetch next (pad covers k=127)
        __syncthreads();
        float xk = sh[k & 1];
        if (i > k) y = fmaf(coef, xk, y);
    }

    if (j < NN) ((float*)g_Ad2)[(j >> 2)*512 + (i << 2) + (j & 3)] = y;
    else        g_Bd[i] = y;
}

// ---------------- phase A: local scans + Ad^32 columns (one launch) ------
// Blocks [0,128): chunk-local scan, emits chunk-end state only.
// Blocks [128,256): column (bid-128) of Ad^32 via 32 iterated matvecs.
// 128 threads, full row in registers (R14's pair-split here regressed:
// shfl lat 26 + wider barriers landed on the serial critical path).
__global__ __launch_bounds__(NN, 1) void k_local32(const float* __restrict__ f) {
    int bid = blockIdx.x;
    int n = threadIdx.x;
    __shared__ double2 cbuf[2][32];
    __shared__ float   fs[CL];

    u64 rl[32], rh[32];
    #pragma unroll
    for (int j = 0; j < 32; j++) {
        double2 t = g_Ad2[j*NN + n];
        rl[j] = __double_as_longlong(t.x);
        rh[j] = __double_as_longlong(t.y);
    }

    bool ispow = (bid >= BATCH*PCH);
    int b = 0, p = 0, jcol = 0;
    float bd = 0.f;
    if (!ispow) {
        b = bid >> 6; p = bid & 63;
        bd = g_Bd[n];
        if (n < CL) fs[n] = f[b*LSEQ + p*CL + n];
        ((float*)cbuf[0])[n] = 0.f;
    } else {
        jcol = bid - BATCH*PCH;
        ((float*)cbuf[0])[n] = (n == jcol) ? 1.f : 0.f;
    }
    __syncthreads();

    int cur = 0;
    float v = 0.f;
    #pragma unroll 1
    for (int i = 0; i < CL; i++) {
        u64 a0 = 0, a1 = 0, a2 = 0, a3 = 0;
        #pragma unroll
        for (int j = 0; j < 32; j += 2) {
            double2 c0 = cbuf[cur][j];
            double2 c1 = cbuf[cur][j+1];
            ffma2(a0, rl[j],   __double_as_longlong(c0.x));
            ffma2(a1, rh[j],   __double_as_longlong(c0.y));
            ffma2(a2, rl[j+1], __double_as_longlong(c1.x));
            ffma2(a3, rh[j+1], __double_as_longlong(c1.y));
        }
        v = ((f2lo(a0)+f2hi(a0)) + (f2lo(a1)+f2hi(a1)))
          + ((f2lo(a2)+f2hi(a2)) + (f2lo(a3)+f2hi(a3)));
        if (!ispow) v += bd * fs[i];
        ((float*)cbuf[cur ^ 1])[n] = v;
        cur ^= 1;
        __syncthreads();
    }

    if (!ispow) g_lend[bid*NN + n] = v;
    else        ((float*)g_M32)[(jcol >> 2)*512 + (n << 2) + (jcol & 3)] = v;
}

// ---------------- phase B: serial carry chain with Ad^32 -----------------
// carry_0 = 0 ; carry_p = Ad^32 * carry_{p-1} + lend_{p-1}. 128 threads,
// full row in registers, all 63 lend vectors prefetched into shared.
__global__ __launch_bounds__(NN, 1) void k_carry() {
    int b = blockIdx.x;
    int n = threadIdx.x;
    __shared__ double2 cbuf[2][32];
    __shared__ float   lend_s[(PCH-1)*NN];   // 32 KB, coalesced prefetch
    u64 rl[32], rh[32];
    #pragma unroll
    for (int j = 0; j < 32; j++) {
        double2 t = g_M32[j*NN + n];
        rl[j] = __double_as_longlong(t.x);
        rh[j] = __double_as_longlong(t.y);
    }
    for (int idx = n; idx < (PCH-1)*NN; idx += NN)
        lend_s[idx] = g_lend[b*PCH*NN + idx];
    ((float*)cbuf[0])[n] = 0.f;
    g_carry[(b*PCH + 0)*NN + n] = 0.f;
    __syncthreads();

    int cur = 0;
    #pragma unroll 1
    for (int p = 1; p < PCH; p++) {
        u64 a0 = 0, a1 = 0, a2 = 0, a3 = 0;
        #pragma unroll
        for (int j = 0; j < 32; j += 2) {
            double2 c0 = cbuf[cur][j];
            double2 c1 = cbuf[cur][j+1];
            ffma2(a0, rl[j],   __double_as_longlong(c0.x));
            ffma2(a1, rh[j],   __double_as_longlong(c0.y));
            ffma2(a2, rl[j+1], __double_as_longlong(c1.x));
            ffma2(a3, rh[j+1], __double_as_longlong(c1.y));
        }
        float v = ((f2lo(a0)+f2hi(a0)) + (f2lo(a1)+f2hi(a1)))
                + ((f2lo(a2)+f2hi(a2)) + (f2lo(a3)+f2hi(a3)))
                + lend_s[(p-1)*NN + n];
        g_carry[(b*PCH + p)*NN + n] = v;
        ((float*)cbuf[cur ^ 1])[n] = v;
        cur ^= 1;
        __syncthreads();
    }
}

// ---------------- phase C: seeded rescan + broadcast write + c_final -----
// Blocks (b,p,h): re-run chunk recurrence seeded with carry_p and write
// N-row half h of every y[b,t,:,:] tile. Pair-split matvec (n=tid>>1,
// half=tid&1, shfl.xor combine) -> 2 blocks/SM -> one co-resident wave.
// Store-first order: stores of state i-1 issued at the TOP of iteration i
// (stable since the previous barrier) so each 32KB burst drains under the
// next matvec. (Isolated win in R13: 49.6 -> 48.1us.)
__global__ __launch_bounds__(256, 2) void k_out(float4* __restrict__ out4,
                                                const float* __restrict__ f,
                                                const float* __restrict__ Cv,
                                                const float* __restrict__ Dv,
                                                int yoff4) {
    int idx = blockIdx.x;
    int b = idx >> 7, ph = idx & 127;
    int p = ph >> 1, h = ph & 1;
    int tid = threadIdx.x;
    int n = tid >> 1, half = tid & 1;
    int w = tid >> 5, lane = tid & 31;
    __shared__ float sbufF[2][NN];
    __shared__ float fs[CL];

    u64 rl[16], rh[16];
    #pragma unroll
    for (int jj = 0; jj < 16; jj++) {
        double2 t = g_Ad2[(16*half + jj)*NN + n];
        rl[jj] = __double_as_longlong(t.x);
        rh[jj] = __double_as_longlong(t.y);
    }
    float bd = g_Bd[n];
    if (tid < CL) fs[tid] = f[b*LSEQ + p*CL + tid];
    float creg[8];
    #pragma unroll
    for (int r2 = 0; r2 < 8; r2++) creg[r2] = Cv[h*64 + w*8 + r2];
    float D0 = Dv[0];

    if (!half) sbufF[1][n] = (p > 0) ? __ldcg(&g_carry[(b*PCH + p)*NN + n]) : 0.f;
    __syncthreads();

    float4* yout = out4 + yoff4 + (size_t)(b*LSEQ + p*CL)*NN*(NN/4);

    #pragma unroll 1
    for (int i = 0; i < CL; i++) {
        int cw = i & 1;          // state i written here
        int cr = cw ^ 1;         // state i-1 / seed (stable since last barrier)

        // stores of state i-1 first (drain overlaps this step's matvec)
        if (i > 0) {
            float4 s4 = ((float4*)sbufF[cr])[lane];
            float dfp = D0 * fs[i-1];
            float4* yrow = yout + (size_t)(i-1)*NN*(NN/4) + (h*64 + w*8)*(NN/4) + lane;
            #pragma unroll
            for (int r2 = 0; r2 < 8; r2++) {
                float cn = creg[r2];
                float4 o;
                o.x = fmaf(cn, s4.x, dfp);  o.y = fmaf(cn, s4.y, dfp);
                o.z = fmaf(cn, s4.z, dfp);  o.w = fmaf(cn, s4.w, dfp);
                __stcs(yrow + (size_t)r2*(NN/4), o);
            }
        }

        const double2* c2 = (const double2*)sbufF[cr] + 16*half;
        u64 a0 = 0, a1 = 0, a2 = 0, a3 = 0;
        #pragma unroll
        for (int jj = 0; jj < 16; jj += 2) {
            double2 c0 = c2[jj], c1 = c2[jj+1];
            ffma2(a0, rl[jj],   __double_as_longlong(c0.x));
            ffma2(a1, rh[jj],   __double_as_longlong(c0.y));
            ffma2(a2, rl[jj+1], __double_as_longlong(c1.x));
            ffma2(a3, rh[jj+1], __double_as_longlong(c1.y));
        }
        float part = ((f2lo(a0)+f2hi(a0)) + (f2lo(a1)+f2hi(a1)))
                   + ((f2lo(a2)+f2hi(a2)) + (f2lo(a3)+f2hi(a3)));
        float other = __shfl_xor_sync(0xffffffffu, part, 1);
        float v = part + other + bd * fs[i];
        if (!half) sbufF[cw][n] = v;
        __syncthreads();
    }

    // epilogue: store state CL-1 (in sbufF[(CL-1)&1])
    {
        int cl = (CL-1) & 1;
        float4 s4 = ((float4*)sbufF[cl])[lane];
        float dfp = D0 * fs[CL-1];
        float4* yrow = yout + (size_t)(CL-1)*NN*(NN/4) + (h*64 + w*8)*(NN/4) + lane;
        #pragma unroll
        for (int r2 = 0; r2 < 8; r2++) {
            float cn = creg[r2];
            float4 o;
            o.x = fmaf(cn, s4.x, dfp);  o.y = fmaf(cn, s4.y, dfp);
            o.z = fmaf(cn, s4.z, dfp);  o.w = fmaf(cn, s4.w, dfp);
            __stcs(yrow + (size_t)r2*(NN/4), o);
        }
        // c_final: last chunk, h==0 block writes S[L-1]
        if (p == PCH-1 && h == 0 && yoff4 >= (BATCH*NN/4) && tid < NN/4) {
            out4[b*(NN/4) + tid] = ((float4*)sbufF[cl])[tid];
        }
    }
}

// ---------------- launcher ----------------
extern "C" void kernel_launch(void* const* d_in, const int* in_sizes, int n_in,
                              void* d_out, int out_size) {
    const float* f  = (const float*)d_in[0];  // (BATCH, L, 1)
    const float* A  = (const float*)d_in[1];  // (N, N)
    const float* Bv = (const float*)d_in[2];  // (N, 1)
    const float* Cv = (const float*)d_in[3];  // (N, 1)
    const float* Dv = (const float*)d_in[4];  // (1,)

    k_solve<<<NN + 1, NN>>>(A, Bv);
    k_local32<<<BATCH*PCH + NN, NN>>>(f);
    k_carry<<<BATCH, NN>>>();

    int ytotal = BATCH * LSEQ * NN * NN;
    int yoff = out_size - ytotal;
    if (yoff < 0) yoff = 0;
    k_out<<<2 * BATCH * PCH, 256>>>((float4*)d_out, f, Cv, Dv, yoff / 4);
}

// round 16
// speedup vs baseline: 1.5322x; 1.5322x over previous
#include <cuda_runtime.h>
#include <cstdint>

#define NN    128
#define BATCH 2
#define LSEQ  2048
#define CL    32
#define PCH   (LSEQ/CL)   // 64 chunks per batch

typedef unsigned long long u64;

// packed f32x2 FMA (sm_103a FFMA2): d.lo += a.lo*b.lo ; d.hi += a.hi*b.hi
__device__ __forceinline__ void ffma2(u64& d, u64 a, u64 b) {
    asm("fma.rn.f32x2 %0, %1, %2, %0;" : "+l"(d) : "l"(a), "l"(b));
}
__device__ __forceinline__ float f2lo(u64 a){ return __int_as_float((int)(unsigned)(a & 0xffffffffull)); }
__device__ __forceinline__ float f2hi(u64 a){ return __int_as_float((int)(unsigned)(a >> 32)); }

// ---------------- device scratch (no allocations allowed) ----------------
// Ad packed: double2 element [m*NN+n] holds Ad[n][4m..4m+3] as 4 floats.
__device__ double2 g_Ad2[32*NN];
__device__ double2 g_M32[32*NN];                  // Ad^32, same layout
__device__ float   g_Bd[NN];
__device__ float   g_lend[BATCH*PCH*NN];          // chunk-end local states
__device__ float   g_carry[BATCH*PCH*NN];

// ---------------- setup: GBT discretization (fp32 forward substitution) --
// P1 = I - 0.5*A is lower triangular (HiPPO-LegS). Block j solves column j
// of P1*Ad = I + 0.5*A (j<128) or P1*Bd = B (j==128). Division-free chain.
__global__ __launch_bounds__(NN) void k_solve(const float* __restrict__ A,
                                              const float* __restrict__ Bv) {
    int j = blockIdx.x, i = threadIdx.x;
    __shared__ float AT_s[NN*(NN+1)/2 + 1];   // packed lower triangle (+1 pad)
    __shared__ float sh[2];

    for (int idx = i; idx < NN*NN; idx += NN) {
        int r = idx >> 7, c = idx & 127;
        if (c <= r) AT_s[r*(r+1)/2 + c] = A[idx];
    }
    __syncthreads();

    int tri_i = i*(i+1)/2;
    float rdiag = 1.f / (1.f - 0.5f * AT_s[tri_i + i]);
    float hrd   = 0.5f * rdiag;

    float rhs;
    if (j < NN) rhs = (i == j ? 1.f : 0.f) + 0.5f * A[i*NN + j];
    else        rhs = Bv[i];
    float y = rhs * rdiag;

    float at = AT_s[tri_i];   // A[i][0]
    #pragma unroll 4
    for (int k = 0; k < NN; k++) {
        float coef = hrd * at;              // off critical path
        if (i == k) sh[k & 1] = y;
        at = AT_s[tri_i + k + 1];           // prefetch next (pad covers k=127)
        __syncthreads();
        float xk = sh[k & 1];
        if (i > k) y = fmaf(coef, xk, y);
    }

    if (j < NN) ((float*)g_Ad2)[(j >> 2)*512 + (i << 2) + (j & 3)] = y;
    else        g_Bd[i] = y;
}

// ---------------- phase A: local scans + Ad^32 columns (one launch) ------
// Blocks [0,128): chunk-local scan, emits chunk-end state only.
// Blocks [128,256): column (bid-128) of Ad^32 via 32 iterated matvecs.
__global__ __launch_bounds__(NN, 1) void k_local32(const float* __restrict__ f) {
    int bid = blockIdx.x;
    int n = threadIdx.x;
    __shared__ double2 cbuf[2][32];
    __shared__ float   fs[CL];

    u64 rl[32], rh[32];
    #pragma unroll
    for (int j = 0; j < 32; j++) {
        double2 t = g_Ad2[j*NN + n];
        rl[j] = __double_as_longlong(t.x);
        rh[j] = __double_as_longlong(t.y);
    }

    bool ispow = (bid >= BATCH*PCH);
    int b = 0, p = 0, jcol = 0;
    float bd = 0.f;
    if (!ispow) {
        b = bid >> 6; p = bid & 63;
        bd = g_Bd[n];
        if (n < CL) fs[n] = f[b*LSEQ + p*CL + n];
        ((float*)cbuf[0])[n] = 0.f;
    } else {
        jcol = bid - BATCH*PCH;
        ((float*)cbuf[0])[n] = (n == jcol) ? 1.f : 0.f;
    }
    __syncthreads();

    int cur = 0;
    float v = 0.f;
    #pragma unroll 1
    for (int i = 0; i < CL; i++) {
        u64 a0 = 0, a1 = 0, a2 = 0, a3 = 0;
        #pragma unroll
        for (int j = 0; j < 32; j += 2) {
            double2 c0 = cbuf[cur][j];
            double2 c1 = cbuf[cur][j+1];
            ffma2(a0, rl[j],   __double_as_longlong(c0.x));
            ffma2(a1, rh[j],   __double_as_longlong(c0.y));
            ffma2(a2, rl[j+1], __double_as_longlong(c1.x));
            ffma2(a3, rh[j+1], __double_as_longlong(c1.y));
        }
        v = ((f2lo(a0)+f2hi(a0)) + (f2lo(a1)+f2hi(a1)))
          + ((f2lo(a2)+f2hi(a2)) + (f2lo(a3)+f2hi(a3)));
        if (!ispow) v += bd * fs[i];
        ((float*)cbuf[cur ^ 1])[n] = v;
        cur ^= 1;
        __syncthreads();
    }

    if (!ispow) g_lend[bid*NN + n] = v;
    else        ((float*)g_M32)[(jcol >> 2)*512 + (n << 2) + (jcol & 3)] = v;
}

// ---------------- phase B: serial carry chain with Ad^32 -----------------
// carry_0 = 0 ; carry_p = Ad^32 * carry_{p-1} + lend_{p-1}. 128 threads,
// full row in registers, all 63 lend vectors prefetched into shared.
__global__ __launch_bounds__(NN, 1) void k_carry() {
    int b = blockIdx.x;
    int n = threadIdx.x;
    __shared__ double2 cbuf[2][32];
    __shared__ float   lend_s[(PCH-1)*NN];   // 32 KB, coalesced prefetch
    u64 rl[32], rh[32];
    #pragma unroll
    for (int j = 0; j < 32; j++) {
        double2 t = g_M32[j*NN + n];
        rl[j] = __double_as_longlong(t.x);
        rh[j] = __double_as_longlong(t.y);
    }
    for (int idx = n; idx < (PCH-1)*NN; idx += NN)
        lend_s[idx] = g_lend[b*PCH*NN + idx];
    ((float*)cbuf[0])[n] = 0.f;
    g_carry[(b*PCH + 0)*NN + n] = 0.f;
    __syncthreads();

    int cur = 0;
    #pragma unroll 1
    for (int p = 1; p < PCH; p++) {
        u64 a0 = 0, a1 = 0, a2 = 0, a3 = 0;
        #pragma unroll
        for (int j = 0; j < 32; j += 2) {
            double2 c0 = cbuf[cur][j];
            double2 c1 = cbuf[cur][j+1];
            ffma2(a0, rl[j],   __double_as_longlong(c0.x));
            ffma2(a1, rh[j],   __double_as_longlong(c0.y));
            ffma2(a2, rl[j+1], __double_as_longlong(c1.x));
            ffma2(a3, rh[j+1], __double_as_longlong(c1.y));
        }
        float v = ((f2lo(a0)+f2hi(a0)) + (f2lo(a1)+f2hi(a1)))
                + ((f2lo(a2)+f2hi(a2)) + (f2lo(a3)+f2hi(a3)))
                + lend_s[(p-1)*NN + n];
        g_carry[(b*PCH + p)*NN + n] = v;
        ((float*)cbuf[cur ^ 1])[n] = v;
        cur ^= 1;
        __syncthreads();
    }
}

// ---------------- phase C: seeded rescan + broadcast write + c_final -----
// Blocks (b,p,h): re-run chunk recurrence seeded with carry_p and write
// N-row half h of every y[b,t,:,:] tile. Pair-split matvec (n=tid>>1,
// half=tid&1, shfl.xor combine) -> 2 blocks/SM -> one co-resident wave.
__global__ __launch_bounds__(256, 2) void k_out(float4* __restrict__ out4,
                                                const float* __restrict__ f,
                                                const float* __restrict__ Cv,
                                                const float* __restrict__ Dv,
                                                int yoff4) {
    int idx = blockIdx.x;
    int b = idx >> 7, ph = idx & 127;
    int p = ph >> 1, h = ph & 1;
    int tid = threadIdx.x;
    int n = tid >> 1, half = tid & 1;
    int w = tid >> 5, lane = tid & 31;
    __shared__ float sbufF[2][NN];
    __shared__ float fs[CL];

    u64 rl[16], rh[16];
    #pragma unroll
    for (int jj = 0; jj < 16; jj++) {
        double2 t = g_Ad2[(16*half + jj)*NN + n];
        rl[jj] = __double_as_longlong(t.x);
        rh[jj] = __double_as_longlong(t.y);
    }
    float bd = g_Bd[n];
    if (tid < CL) fs[tid] = f[b*LSEQ + p*CL + tid];
    float creg[8];
    #pragma unroll
    for (int r2 = 0; r2 < 8; r2++) creg[r2] = Cv[h*64 + w*8 + r2];
    float D0 = Dv[0];

    if (!half) sbufF[1][n] = (p > 0) ? __ldcg(&g_carry[(b*PCH + p)*NN + n]) : 0.f;
    __syncthreads();

    float4* yout = out4 + yoff4 + (size_t)(b*LSEQ + p*CL)*NN*(NN/4);

    #pragma unroll 1
    for (int i = 0; i < CL; i++) {
        int cw = i & 1;          // state i written this step
        int cr = cw ^ 1;         // previous state buffer
        const double2* c2 = (const double2*)sbufF[cr] + 16*half;
        u64 a0 = 0, a1 = 0, a2 = 0, a3 = 0;
        #pragma unroll
        for (int jj = 0; jj < 16; jj += 2) {
            double2 c0 = c2[jj], c1 = c2[jj+1];
            ffma2(a0, rl[jj],   __double_as_longlong(c0.x));
            ffma2(a1, rh[jj],   __double_as_longlong(c0.y));
            ffma2(a2, rl[jj+1], __double_as_longlong(c1.x));
            ffma2(a3, rh[jj+1], __double_as_longlong(c1.y));
        }
        float part = ((f2lo(a0)+f2hi(a0)) + (f2lo(a1)+f2hi(a1)))
                   + ((f2lo(a2)+f2hi(a2)) + (f2lo(a3)+f2hi(a3)));
        float other = __shfl_xor_sync(0xffffffffu, part, 1);
        float fsv = fs[i];
        float v = part + other + bd * fsv;
        if (!half) sbufF[cw][n] = v;
        __syncthreads();

        float4 s4 = ((float4*)sbufF[cw])[lane];
        float df = D0 * fsv;
        float4* yrow = yout + (size_t)i*NN*(NN/4) + (h*64 + w*8)*(NN/4) + lane;
        #pragma unroll
        for (int r2 = 0; r2 < 8; r2++) {
            float cn = creg[r2];
            float4 o;
            o.x = fmaf(cn, s4.x, df);  o.y = fmaf(cn, s4.y, df);
            o.z = fmaf(cn, s4.z, df);  o.w = fmaf(cn, s4.w, df);
            __stcs(yrow + (size_t)r2*(NN/4), o);
        }
    }

    // c_final: last chunk, h==0 block writes S[L-1] (in sbufF[(CL-1)&1])
    if (p == PCH-1 && h == 0 && yoff4 >= (BATCH*NN/4) && tid < NN/4) {
        out4[b*(NN/4) + tid] = ((float4*)sbufF[(CL-1) & 1])[tid];
    }
}

// ---------------- launcher ----------------
extern "C" void kernel_launch(void* const* d_in, const int* in_sizes, int n_in,
                              void* d_out, int out_size) {
    const float* f  = (const float*)d_in[0];  // (BATCH, L, 1)
    const float* A  = (const float*)d_in[1];  // (N, N)
    const float* Bv = (const float*)d_in[2];  // (N, 1)
    const float* Cv = (const float*)d_in[3];  // (N, 1)
    const float* Dv = (const float*)d_in[4];  // (1,)

    k_solve<<<NN + 1, NN>>>(A, Bv);
    k_local32<<<BATCH*PCH + NN, NN>>>(f);
    k_carry<<<BATCH, NN>>>();

    int ytotal = BATCH * LSEQ * NN * NN;
    int yoff = out_size - ytotal;
    if (yoff < 0) yoff = 0;
    k_out<<<2 * BATCH * PCH, 256>>>((float4*)d_out, f, Cv, Dv, yoff / 4);
}